// round 16
// baseline (speedup 1.0000x reference)
#include <cuda_runtime.h>
#include <cuda_bf16.h>
#include <math.h>
#include <stdint.h>

#define N_TOTAL 12160
#define EMB     512
#define ESM     1280
#define HEADS   8
#define HD      64
#define NGRAPH  32

typedef __nv_bfloat16 bf16;

// ---------------- scratch (no cudaMalloc allowed) ----------------
__device__ bf16  g_esm_bf [N_TOTAL * ESM];
__device__ bf16  g_h_bf   [N_TOTAL * EMB];
__device__ bf16  g_Wesm_bf[EMB * ESM];
__device__ bf16  g_Wq_bf  [EMB * EMB];
__device__ bf16  g_Wkv_bf [2 * EMB * EMB];
__device__ bf16  g_Wo_bf  [EMB * EMB];
__device__ bf16  g_hesm_bf[N_TOTAL * EMB];
__device__ bf16  g_q_bf   [N_TOTAL * EMB];
__device__ bf16  g_k_bf   [N_TOTAL * EMB];
__device__ bf16  g_v_bf   [N_TOTAL * EMB];
__device__ bf16  g_ab_bf  [N_TOTAL * EMB];
__device__ bf16  g_ob_bf  [N_TOTAL * EMB];

// ---------------- helpers ----------------
__device__ __forceinline__ uint32_t packbf(float hi, float lo) {
    uint32_t d;
    asm("cvt.rn.bf16x2.f32 %0, %1, %2;" : "=r"(d) : "f"(hi), "f"(lo));
    return d;
}

__device__ __forceinline__ void mma_bf16(float& d0, float& d1, float& d2, float& d3,
                                         uint32_t a0, uint32_t a1, uint32_t a2, uint32_t a3,
                                         uint32_t b0, uint32_t b1)
{
    asm volatile(
        "mma.sync.aligned.m16n8k16.row.col.f32.bf16.bf16.f32 "
        "{%0,%1,%2,%3}, {%4,%5,%6,%7}, {%8,%9}, {%0,%1,%2,%3};\n"
        : "+f"(d0), "+f"(d1), "+f"(d2), "+f"(d3)
        : "r"(a0), "r"(a1), "r"(a2), "r"(a3), "r"(b0), "r"(b1));
}

__device__ __forceinline__ void cp_async16(uint32_t smem_addr, const void* gptr) {
    asm volatile("cp.async.cg.shared.global [%0], [%1], 16;\n"
                 :: "r"(smem_addr), "l"(gptr));
}

__device__ __forceinline__ void ldsm_x4(uint32_t& r0, uint32_t& r1, uint32_t& r2, uint32_t& r3,
                                        uint32_t addr)
{
    asm volatile("ldmatrix.sync.aligned.m8n8.x4.shared.b16 {%0,%1,%2,%3}, [%4];\n"
                 : "=r"(r0), "=r"(r1), "=r"(r2), "=r"(r3) : "r"(addr));
}

__device__ __forceinline__ void ldsm_x4_t(uint32_t& r0, uint32_t& r1, uint32_t& r2, uint32_t& r3,
                                          uint32_t addr)
{
    asm volatile("ldmatrix.sync.aligned.m8n8.x4.trans.shared.b16 {%0,%1,%2,%3}, [%4];\n"
                 : "=r"(r0), "=r"(r1), "=r"(r2), "=r"(r3) : "r"(addr));
}

// ---------------------------------------------------------------------------
// Fused fp32 -> bf16 conversion, 16 elems/thread.
// ---------------------------------------------------------------------------
#define D_ESM   972800
#define D_H     389120
#define D_WESM   40960
#define D_W      16384
#define E0 (D_ESM)
#define E1 (E0 + D_H)
#define E2 (E1 + D_WESM)
#define E3 (E2 + D_W)
#define E4 (E3 + D_W)
#define E5 (E4 + D_W)
#define E6 (E5 + D_W)

__global__ __launch_bounds__(256)
void convert_all(const float* __restrict__ esm, const float* __restrict__ h,
                 const float* __restrict__ Wesm, const float* __restrict__ Wq,
                 const float* __restrict__ Wk, const float* __restrict__ Wv,
                 const float* __restrict__ Wo,
                 bf16* __restrict__ esm_bf, bf16* __restrict__ h_bf,
                 bf16* __restrict__ Wesm_bf, bf16* __restrict__ Wq_bf,
                 bf16* __restrict__ Wkv_bf, bf16* __restrict__ Wo_bf)
{
    int i = blockIdx.x * 256 + threadIdx.x;
    if (i >= E6) return;
    const float* src; bf16* dst; int rel;
    if      (i < E0) { src = esm;  dst = esm_bf;               rel = i; }
    else if (i < E1) { src = h;    dst = h_bf;                 rel = i - E0; }
    else if (i < E2) { src = Wesm; dst = Wesm_bf;              rel = i - E1; }
    else if (i < E3) { src = Wq;   dst = Wq_bf;                rel = i - E2; }
    else if (i < E4) { src = Wk;   dst = Wkv_bf;               rel = i - E3; }
    else if (i < E5) { src = Wv;   dst = Wkv_bf + EMB * EMB;   rel = i - E4; }
    else             { src = Wo;   dst = Wo_bf;                rel = i - E5; }

    const float4* p = (const float4*)src + rel * 4;
    float4 a = p[0], b = p[1], c = p[2], d = p[3];
    uint4 o0, o1;
    o0.x = packbf(a.y, a.x); o0.y = packbf(a.w, a.z);
    o0.z = packbf(b.y, b.x); o0.w = packbf(b.w, b.z);
    o1.x = packbf(c.y, c.x); o1.y = packbf(c.w, c.z);
    o1.z = packbf(d.y, d.x); o1.w = packbf(d.w, d.z);
    uint4* q = (uint4*)dst + rel * 2;
    q[0] = o0; q[1] = o1;
}

// ---------------------------------------------------------------------------
// gemm64: dual-job bf16 GEMM, BM=64, BN=128, BK=64, 2-stage, 3 CTAs/SM.
// Per-job K. Warp tile 16x64. bf16 output. Used for ALL GEMM launches.
// ---------------------------------------------------------------------------
#define GBK 64
#define GROW32 36
#define G64_A_U32 (64 * GROW32)    // 2304
#define G64_B_U32 (128 * GROW32)   // 4608
#define G64_SMEM ((2 * G64_A_U32 + 2 * G64_B_U32) * 4)   // 55296 B

__global__ __launch_bounds__(256, 3)
void gemm64(const bf16* __restrict__ A0, const bf16* __restrict__ B0,
            const float* __restrict__ bias0, bf16* __restrict__ Cb0,
            float scale0, int K0,
            const bf16* __restrict__ A1, const bf16* __restrict__ B1,
            const float* __restrict__ bias1, bf16* __restrict__ Cb1,
            float scale1, int K1,
            int ycut)
{
    extern __shared__ uint32_t smem_g[];
    uint32_t* As[2] = { smem_g, smem_g + G64_A_U32 };
    uint32_t* Bs[2] = { smem_g + 2 * G64_A_U32,
                        smem_g + 2 * G64_A_U32 + G64_B_U32 };

    const int tid    = threadIdx.x;
    const int lane   = tid & 31;
    const int warp   = tid >> 5;
    const int g      = lane >> 2;
    const int t      = lane & 3;
    const int warp_m = (warp & 3) * 16;
    const int warp_n = (warp >> 2) * 64;
    const int bm0    = blockIdx.x * 64;

    const bool j1 = ((int)blockIdx.y >= ycut);
    const bf16*  A     = j1 ? A1     : A0;
    const bf16*  Bw    = j1 ? B1     : B0;
    const float* bias  = j1 ? bias1  : bias0;
    bf16*        Cb    = j1 ? Cb1    : Cb0;
    const float  scale = j1 ? scale1 : scale0;
    const int    K     = j1 ? K1     : K0;
    const int    bn0   = (j1 ? (blockIdx.y - ycut) : blockIdx.y) * 128;

    float acc[8][4];
#pragma unroll
    for (int j = 0; j < 8; j++)
#pragma unroll
        for (int c = 0; c < 4; c++) acc[j][c] = 0.0f;

    const int kt_total = K / GBK;

    auto load_stage = [&](int kt, int buf) {
        int k0 = kt * GBK;
#pragma unroll
        for (int r = 0; r < 2; r++) {
            int c   = tid + r * 256;
            int row = c >> 3;
            int q16 = c & 7;
            uint32_t da = (uint32_t)__cvta_generic_to_shared(
                &As[buf][row * GROW32 + q16 * 4]);
            cp_async16(da, A + (size_t)(bm0 + row) * K + k0 + q16 * 8);
        }
#pragma unroll
        for (int r = 0; r < 4; r++) {
            int c   = tid + r * 256;
            int row = c >> 3;
            int q16 = c & 7;
            uint32_t db = (uint32_t)__cvta_generic_to_shared(
                &Bs[buf][row * GROW32 + q16 * 4]);
            cp_async16(db, Bw + (size_t)(bn0 + row) * K + k0 + q16 * 8);
        }
    };

    load_stage(0, 0);
    asm volatile("cp.async.commit_group;\n");

    const int arow_l = (lane & 7) + ((lane & 8) ? 8 : 0);
    const int adim_l = (lane & 16) ? 8 : 0;
    const int brow_l = (lane & 7) + ((lane & 16) ? 8 : 0);
    const int bdim_l = (lane & 8) ? 8 : 0;

    int buf = 0;
    for (int kt = 0; kt < kt_total; kt++) {
        asm volatile("cp.async.wait_group 0;\n");
        __syncthreads();
        if (kt + 1 < kt_total) {
            load_stage(kt + 1, buf ^ 1);
            asm volatile("cp.async.commit_group;\n");
        }
        const bf16* abuf = (const bf16*)As[buf];
        const bf16* bbuf = (const bf16*)Bs[buf];
#pragma unroll
        for (int kg = 0; kg < 4; kg++) {
            uint32_t af[4];
            {
                int arow = warp_m + arow_l;
                uint32_t addr = (uint32_t)__cvta_generic_to_shared(
                    abuf + arow * 72 + kg * 16 + adim_l);
                ldsm_x4(af[0], af[1], af[2], af[3], addr);
            }
            uint32_t bfr[4][4];
#pragma unroll
            for (int nt2 = 0; nt2 < 4; nt2++) {
                int brow = warp_n + nt2 * 16 + brow_l;
                uint32_t addr = (uint32_t)__cvta_generic_to_shared(
                    bbuf + brow * 72 + kg * 16 + bdim_l);
                ldsm_x4(bfr[nt2][0], bfr[nt2][1], bfr[nt2][2], bfr[nt2][3], addr);
            }
#pragma unroll
            for (int nt2 = 0; nt2 < 4; nt2++) {
                mma_bf16(acc[2*nt2][0], acc[2*nt2][1], acc[2*nt2][2], acc[2*nt2][3],
                         af[0], af[1], af[2], af[3], bfr[nt2][0], bfr[nt2][1]);
                mma_bf16(acc[2*nt2+1][0], acc[2*nt2+1][1], acc[2*nt2+1][2], acc[2*nt2+1][3],
                         af[0], af[1], af[2], af[3], bfr[nt2][2], bfr[nt2][3]);
            }
        }
        buf ^= 1;
    }

    const int row0 = bm0 + warp_m + g;
#pragma unroll
    for (int nt = 0; nt < 8; nt++) {
        int col = bn0 + warp_n + nt * 8 + t * 2;
        float2 bb = *(const float2*)(bias + col);
        float o00 = (acc[nt][0] + bb.x) * scale;
        float o01 = (acc[nt][1] + bb.y) * scale;
        float o10 = (acc[nt][2] + bb.x) * scale;
        float o11 = (acc[nt][3] + bb.y) * scale;
        *(uint32_t*)((uint16_t*)Cb + (size_t)row0 * EMB + col)       = packbf(o01, o00);
        *(uint32_t*)((uint16_t*)Cb + (size_t)(row0 + 8) * EMB + col) = packbf(o11, o10);
    }
}

// ---------------------------------------------------------------------------
// bf16 flash attention (R13): no-max exp2 softmax, split-half S/PV, 3 CTAs/SM.
// ---------------------------------------------------------------------------
#define FSTR32 36
#define ROWB   144

__global__ __launch_bounds__(256, 3)
void flash_bf16(const bf16* __restrict__ q, const bf16* __restrict__ k,
                const bf16* __restrict__ v, bf16* __restrict__ outp)
{
    const int b    = NGRAPH - 1 - blockIdx.x;
    const int h    = blockIdx.y;
    const int tile = blockIdx.z;
    const int len  = 256 + 8 * b;
    if (tile * 128 >= len) return;
    const int off  = 256 * b + 4 * b * (b - 1);

    const int tid  = threadIdx.x;
    const int lane = tid & 31;
    const int warp = tid >> 5;
    const int g    = lane >> 2;
    const int t    = lane & 3;

    __shared__ uint32_t Qs[128 * FSTR32];
    __shared__ uint32_t Ks[2][64 * FSTR32];
    __shared__ uint32_t Vs[2][64 * FSTR32];

    const uint32_t qbase  = (uint32_t)__cvta_generic_to_shared(Qs);
    const uint32_t kbase0 = (uint32_t)__cvta_generic_to_shared(Ks[0]);
    const uint32_t kbase1 = (uint32_t)__cvta_generic_to_shared(Ks[1]);
    const uint32_t vbase0 = (uint32_t)__cvta_generic_to_shared(Vs[0]);
    const uint32_t vbase1 = (uint32_t)__cvta_generic_to_shared(Vs[1]);

#pragma unroll
    for (int r = 0; r < 4; r++) {
        int c   = tid + r * 256;
        int row = c >> 3;
        int q16 = c & 7;
        int grow = off + min(tile * 128 + row, len - 1);
        cp_async16(qbase + row * ROWB + q16 * 16,
                   q + (size_t)grow * EMB + h * HD + q16 * 8);
    }
    asm volatile("cp.async.commit_group;\n");

    const int ntiles = (len + 63) >> 6;

    auto load_kv = [&](int jt, uint32_t kb, uint32_t vb) {
        int j0 = jt * 64;
        int cnt = min(64, len - j0);
#pragma unroll
        for (int r = 0; r < 2; r++) {
            int c   = tid + r * 256;
            int row = c >> 3;
            int q16 = c & 7;
            int grow = off + j0 + min(row, cnt - 1);
            cp_async16(kb + row * ROWB + q16 * 16,
                       k + (size_t)grow * EMB + h * HD + q16 * 8);
            cp_async16(vb + row * ROWB + q16 * 16,
                       v + (size_t)grow * EMB + h * HD + q16 * 8);
        }
    };

    load_kv(0, kbase0, vbase0);
    asm volatile("cp.async.commit_group;\n");

    asm volatile("cp.async.wait_group 1;\n");
    __syncthreads();

    uint32_t qf[4][4];
    {
        int arow = warp * 16 + (lane & 7) + ((lane & 8) ? 8 : 0);
        uint32_t a0 = qbase + arow * ROWB + ((lane & 16) ? 16 : 0);
#pragma unroll
        for (int kg = 0; kg < 4; kg++)
            ldsm_x4(qf[kg][0], qf[kg][1], qf[kg][2], qf[kg][3], a0 + kg * 32);
    }

    float oacc[8][4];
#pragma unroll
    for (int nt = 0; nt < 8; nt++)
#pragma unroll
        for (int c = 0; c < 4; c++) oacc[nt][c] = 0.0f;
    float l0 = 0.0f, l1 = 0.0f;

    const uint32_t koff = ((lane & 7) + ((lane & 16) ? 8 : 0)) * ROWB + ((lane & 8) ? 16 : 0);
    const uint32_t voff = ((lane & 7) + ((lane & 8) ? 8 : 0)) * ROWB + ((lane & 16) ? 16 : 0);

    for (int jt = 0; jt < ntiles; jt++) {
        const int cnt = min(64, len - jt * 64);
        const uint32_t kb = (jt & 1) ? kbase1 : kbase0;
        const uint32_t vb = (jt & 1) ? vbase1 : vbase0;

        asm volatile("cp.async.wait_group 0;\n");
        __syncthreads();
        if (jt + 1 < ntiles) {
            load_kv(jt + 1, (jt & 1) ? kbase0 : kbase1, (jt & 1) ? vbase0 : vbase1);
            asm volatile("cp.async.commit_group;\n");
        }

        const uint32_t kl = kb + koff;
        const uint32_t vl = vb + voff;

#pragma unroll
        for (int half = 0; half < 2; half++) {
            if (half * 32 >= cnt) break;
            const uint32_t klh = kl + half * (32 * ROWB);
            const uint32_t vlh = vl + half * (32 * ROWB);

            float cf[4][4];
#pragma unroll
            for (int nt = 0; nt < 4; nt++)
                cf[nt][0] = cf[nt][1] = cf[nt][2] = cf[nt][3] = 0.0f;

#pragma unroll
            for (int nt2 = 0; nt2 < 2; nt2++) {
                if (half * 32 + nt2 * 16 >= cnt) break;
#pragma unroll
                for (int kg = 0; kg < 4; kg++) {
                    uint32_t b00, b01, b10, b11;
                    ldsm_x4(b00, b01, b10, b11, klh + nt2 * (16 * ROWB) + kg * 32);
                    mma_bf16(cf[2*nt2][0], cf[2*nt2][1], cf[2*nt2][2], cf[2*nt2][3],
                             qf[kg][0], qf[kg][1], qf[kg][2], qf[kg][3], b00, b01);
                    mma_bf16(cf[2*nt2+1][0], cf[2*nt2+1][1], cf[2*nt2+1][2], cf[2*nt2+1][3],
                             qf[kg][0], qf[kg][1], qf[kg][2], qf[kg][3], b10, b11);
                }
            }
#pragma unroll
            for (int nt = 0; nt < 4; nt++)
                if (half * 32 + nt * 8 >= cnt)
                    cf[nt][0] = cf[nt][1] = cf[nt][2] = cf[nt][3] = -1e30f;

#pragma unroll
            for (int nt = 0; nt < 4; nt++) {
                cf[nt][0] = exp2f(cf[nt][0]);
                cf[nt][1] = exp2f(cf[nt][1]);
                cf[nt][2] = exp2f(cf[nt][2]);
                cf[nt][3] = exp2f(cf[nt][3]);
                l0 += cf[nt][0] + cf[nt][1];
                l1 += cf[nt][2] + cf[nt][3];
            }

#pragma unroll
            for (int kc = 0; kc < 2; kc++) {
                if (half * 32 + kc * 16 >= cnt) break;
                uint32_t a0 = packbf(cf[2*kc][1],   cf[2*kc][0]);
                uint32_t a1 = packbf(cf[2*kc][3],   cf[2*kc][2]);
                uint32_t a2 = packbf(cf[2*kc+1][1], cf[2*kc+1][0]);
                uint32_t a3 = packbf(cf[2*kc+1][3], cf[2*kc+1][2]);
#pragma unroll
                for (int nt2 = 0; nt2 < 4; nt2++) {
                    uint32_t b00, b01, b10, b11;
                    ldsm_x4_t(b00, b01, b10, b11, vlh + kc * (16 * ROWB) + nt2 * 32);
                    mma_bf16(oacc[2*nt2][0], oacc[2*nt2][1], oacc[2*nt2][2], oacc[2*nt2][3],
                             a0, a1, a2, a3, b00, b01);
                    mma_bf16(oacc[2*nt2+1][0], oacc[2*nt2+1][1], oacc[2*nt2+1][2], oacc[2*nt2+1][3],
                             a0, a1, a2, a3, b10, b11);
                }
            }
        }
    }

    l0 += __shfl_xor_sync(0xffffffffu, l0, 1);
    l0 += __shfl_xor_sync(0xffffffffu, l0, 2);
    l1 += __shfl_xor_sync(0xffffffffu, l1, 1);
    l1 += __shfl_xor_sync(0xffffffffu, l1, 2);

    const float li0 = 1.0f / l0;
    const float li1 = 1.0f / l1;
    const int qrow0 = tile * 128 + warp * 16 + g;
    uint16_t* ob = (uint16_t*)outp;
#pragma unroll
    for (int nt = 0; nt < 8; nt++) {
        int col = h * HD + nt * 8 + t * 2;
        if (qrow0 < len)
            *(uint32_t*)(ob + (size_t)(off + qrow0) * EMB + col) =
                packbf(oacc[nt][1] * li0, oacc[nt][0] * li0);
        if (qrow0 + 8 < len)
            *(uint32_t*)(ob + (size_t)(off + qrow0 + 8) * EMB + col) =
                packbf(oacc[nt][3] * li1, oacc[nt][2] * li1);
    }
}

// ---------------------------------------------------------------------------
// Residual + LayerNorm: x in bf16, residual fp32, out fp32. 2 rows per block.
// ---------------------------------------------------------------------------
__global__ __launch_bounds__(256)
void ln_kernel(const bf16* __restrict__ x, const float* __restrict__ res,
               const float* __restrict__ gamma, const float* __restrict__ beta,
               float* __restrict__ outp)
{
    const int half = threadIdx.x >> 7;
    const int row  = blockIdx.x * 2 + half;
    const int tid  = threadIdx.x & 127;

    uint2 xb = *(const uint2*)((const uint16_t*)x + (size_t)row * EMB + tid * 4);
    float x0 = __uint_as_float(xb.x << 16);
    float x1 = __uint_as_float(xb.x & 0xffff0000u);
    float x2 = __uint_as_float(xb.y << 16);
    float x3 = __uint_as_float(xb.y & 0xffff0000u);
    float4 rv = *(const float4*)(res + (size_t)row * EMB + tid * 4);
    float v0 = x0 + rv.x, v1 = x1 + rv.y, v2 = x2 + rv.z, v3 = x3 + rv.w;

    float s  = v0 + v1 + v2 + v3;
    float sq = v0*v0 + v1*v1 + v2*v2 + v3*v3;
#pragma unroll
    for (int o2 = 16; o2 > 0; o2 >>= 1) {
        s  += __shfl_xor_sync(0xffffffffu, s,  o2);
        sq += __shfl_xor_sync(0xffffffffu, sq, o2);
    }
    __shared__ float ss[8], ssq[8];
    int w = threadIdx.x >> 5;
    if ((threadIdx.x & 31) == 0) { ss[w] = s; ssq[w] = sq; }
    __syncthreads();
    int wb = half * 4;
    s  = ss[wb]  + ss[wb+1]  + ss[wb+2]  + ss[wb+3];
    sq = ssq[wb] + ssq[wb+1] + ssq[wb+2] + ssq[wb+3];

    float mu   = s * (1.0f / 512.0f);
    float var  = sq * (1.0f / 512.0f) - mu * mu;
    float rstd = rsqrtf(var + 1e-5f);

    float4 gv = *(const float4*)(gamma + tid * 4);
    float4 bv = *(const float4*)(beta  + tid * 4);
    float4 o;
    o.x = (v0 - mu) * rstd * gv.x + bv.x;
    o.y = (v1 - mu) * rstd * gv.y + bv.y;
    o.z = (v2 - mu) * rstd * gv.z + bv.z;
    o.w = (v3 - mu) * rstd * gv.w + bv.w;
    *(float4*)(outp + (size_t)row * EMB + tid * 4) = o;
}

// ---------------------------------------------------------------------------
extern "C" void kernel_launch(void* const* d_in, const int* in_sizes, int n_in,
                              void* d_out, int out_size)
{
    const float* esm   = (const float*)d_in[0];
    const float* h     = (const float*)d_in[1];
    const float* W_esm = (const float*)d_in[2];
    const float* b_esm = (const float*)d_in[3];
    const float* Wq    = (const float*)d_in[4];
    const float* bq    = (const float*)d_in[5];
    const float* Wk    = (const float*)d_in[6];
    const float* bk    = (const float*)d_in[7];
    const float* Wv    = (const float*)d_in[8];
    const float* bv    = (const float*)d_in[9];
    const float* Wo    = (const float*)d_in[10];
    const float* bo    = (const float*)d_in[11];
    const float* gamma = (const float*)d_in[12];
    const float* beta  = (const float*)d_in[13];
    float* out = (float*)d_out;

    bf16 *esm_bf, *h_bf, *Wesm_bf, *Wq_bf, *Wkv_bf, *Wo_bf;
    bf16 *hesm_bf, *q_bf, *k_bf, *v_bf, *ab_bf, *ob_bf;
    cudaGetSymbolAddress((void**)&esm_bf,  g_esm_bf);
    cudaGetSymbolAddress((void**)&h_bf,    g_h_bf);
    cudaGetSymbolAddress((void**)&Wesm_bf, g_Wesm_bf);
    cudaGetSymbolAddress((void**)&Wq_bf,   g_Wq_bf);
    cudaGetSymbolAddress((void**)&Wkv_bf,  g_Wkv_bf);
    cudaGetSymbolAddress((void**)&Wo_bf,   g_Wo_bf);
    cudaGetSymbolAddress((void**)&hesm_bf, g_hesm_bf);
    cudaGetSymbolAddress((void**)&q_bf,    g_q_bf);
    cudaGetSymbolAddress((void**)&k_bf,    g_k_bf);
    cudaGetSymbolAddress((void**)&v_bf,    g_v_bf);
    cudaGetSymbolAddress((void**)&ab_bf,   g_ab_bf);
    cudaGetSymbolAddress((void**)&ob_bf,   g_ob_bf);

    cudaFuncSetAttribute(gemm64, cudaFuncAttributeMaxDynamicSharedMemorySize,
                         G64_SMEM);

    convert_all<<<(E6 + 255) / 256, 256>>>(esm, h, W_esm, Wq, Wk, Wv, Wo,
                                           esm_bf, h_bf, Wesm_bf, Wq_bf, Wkv_bf, Wo_bf);

    const float QSCALE = 0.125f * 1.4426950408889634f;

    // Launch A: ESM projection (K=1280) + Q projection (K=512)
    gemm64<<<dim3(N_TOTAL / 64, 8), 256, G64_SMEM>>>(
        esm_bf, Wesm_bf, b_esm, hesm_bf, 1.0f,   ESM,
        h_bf,   Wq_bf,   bq,    q_bf,    QSCALE, EMB,
        4);

    // Launch B: K + V projections
    gemm64<<<dim3(N_TOTAL / 64, 8), 256, G64_SMEM>>>(
        hesm_bf, Wkv_bf,           bk, k_bf, 1.0f, EMB,
        hesm_bf, Wkv_bf + EMB*EMB, bv, v_bf, 1.0f, EMB,
        4);

    flash_bf16<<<dim3(NGRAPH, HEADS, 4), 256>>>(q_bf, k_bf, v_bf, ab_bf);

    // Launch C: Wo projection
    gemm64<<<dim3(N_TOTAL / 64, 4), 256, G64_SMEM>>>(
        ab_bf, Wo_bf, bo, ob_bf, 1.0f, EMB,
        ab_bf, Wo_bf, bo, ob_bf, 1.0f, EMB,
        4);

    ln_kernel<<<N_TOTAL / 2, 256>>>(ob_bf, h, gamma, beta, out);
}

// round 17
// speedup vs baseline: 1.0713x; 1.0713x over previous
#include <cuda_runtime.h>
#include <cuda_bf16.h>
#include <math.h>
#include <stdint.h>

#define N_TOTAL 12160
#define EMB     512
#define ESM     1280
#define HEADS   8
#define HD      64
#define NGRAPH  32

typedef __nv_bfloat16 bf16;

// ---------------- scratch (no cudaMalloc allowed) ----------------
__device__ bf16  g_esm_bf [N_TOTAL * ESM];
__device__ bf16  g_h_bf   [N_TOTAL * EMB];
__device__ bf16  g_Wesm_bf[EMB * ESM];
__device__ bf16  g_Wq_bf  [EMB * EMB];
__device__ bf16  g_Wkv_bf [2 * EMB * EMB];
__device__ bf16  g_Wo_bf  [EMB * EMB];
__device__ bf16  g_hesm_bf[N_TOTAL * EMB];
__device__ bf16  g_q_bf   [N_TOTAL * EMB];
__device__ bf16  g_k_bf   [N_TOTAL * EMB];
__device__ bf16  g_v_bf   [N_TOTAL * EMB];
__device__ bf16  g_ab_bf  [N_TOTAL * EMB];
__device__ bf16  g_ob_bf  [N_TOTAL * EMB];

// ---------------- helpers ----------------
__device__ __forceinline__ uint32_t packbf(float hi, float lo) {
    uint32_t d;
    asm("cvt.rn.bf16x2.f32 %0, %1, %2;" : "=r"(d) : "f"(hi), "f"(lo));
    return d;
}

__device__ __forceinline__ void mma_bf16(float& d0, float& d1, float& d2, float& d3,
                                         uint32_t a0, uint32_t a1, uint32_t a2, uint32_t a3,
                                         uint32_t b0, uint32_t b1)
{
    asm volatile(
        "mma.sync.aligned.m16n8k16.row.col.f32.bf16.bf16.f32 "
        "{%0,%1,%2,%3}, {%4,%5,%6,%7}, {%8,%9}, {%0,%1,%2,%3};\n"
        : "+f"(d0), "+f"(d1), "+f"(d2), "+f"(d3)
        : "r"(a0), "r"(a1), "r"(a2), "r"(a3), "r"(b0), "r"(b1));
}

__device__ __forceinline__ void cp_async16(uint32_t smem_addr, const void* gptr) {
    asm volatile("cp.async.cg.shared.global [%0], [%1], 16;\n"
                 :: "r"(smem_addr), "l"(gptr));
}

__device__ __forceinline__ void ldsm_x4(uint32_t& r0, uint32_t& r1, uint32_t& r2, uint32_t& r3,
                                        uint32_t addr)
{
    asm volatile("ldmatrix.sync.aligned.m8n8.x4.shared.b16 {%0,%1,%2,%3}, [%4];\n"
                 : "=r"(r0), "=r"(r1), "=r"(r2), "=r"(r3) : "r"(addr));
}

__device__ __forceinline__ void ldsm_x4_t(uint32_t& r0, uint32_t& r1, uint32_t& r2, uint32_t& r3,
                                          uint32_t addr)
{
    asm volatile("ldmatrix.sync.aligned.m8n8.x4.trans.shared.b16 {%0,%1,%2,%3}, [%4];\n"
                 : "=r"(r0), "=r"(r1), "=r"(r2), "=r"(r3) : "r"(addr));
}

// ---------------------------------------------------------------------------
// Fused fp32 -> bf16 conversion, 16 elems/thread.
// ---------------------------------------------------------------------------
#define D_ESM   972800
#define D_H     389120
#define D_WESM   40960
#define D_W      16384
#define E0 (D_ESM)
#define E1 (E0 + D_H)
#define E2 (E1 + D_WESM)
#define E3 (E2 + D_W)
#define E4 (E3 + D_W)
#define E5 (E4 + D_W)
#define E6 (E5 + D_W)

__global__ __launch_bounds__(256)
void convert_all(const float* __restrict__ esm, const float* __restrict__ h,
                 const float* __restrict__ Wesm, const float* __restrict__ Wq,
                 const float* __restrict__ Wk, const float* __restrict__ Wv,
                 const float* __restrict__ Wo,
                 bf16* __restrict__ esm_bf, bf16* __restrict__ h_bf,
                 bf16* __restrict__ Wesm_bf, bf16* __restrict__ Wq_bf,
                 bf16* __restrict__ Wkv_bf, bf16* __restrict__ Wo_bf)
{
    int i = blockIdx.x * 256 + threadIdx.x;
    if (i >= E6) return;
    const float* src; bf16* dst; int rel;
    if      (i < E0) { src = esm;  dst = esm_bf;               rel = i; }
    else if (i < E1) { src = h;    dst = h_bf;                 rel = i - E0; }
    else if (i < E2) { src = Wesm; dst = Wesm_bf;              rel = i - E1; }
    else if (i < E3) { src = Wq;   dst = Wq_bf;                rel = i - E2; }
    else if (i < E4) { src = Wk;   dst = Wkv_bf;               rel = i - E3; }
    else if (i < E5) { src = Wv;   dst = Wkv_bf + EMB * EMB;   rel = i - E4; }
    else             { src = Wo;   dst = Wo_bf;                rel = i - E5; }

    const float4* p = (const float4*)src + rel * 4;
    float4 a = p[0], b = p[1], c = p[2], d = p[3];
    uint4 o0, o1;
    o0.x = packbf(a.y, a.x); o0.y = packbf(a.w, a.z);
    o0.z = packbf(b.y, b.x); o0.w = packbf(b.w, b.z);
    o1.x = packbf(c.y, c.x); o1.y = packbf(c.w, c.z);
    o1.z = packbf(d.y, d.x); o1.w = packbf(d.w, d.z);
    uint4* q = (uint4*)dst + rel * 2;
    q[0] = o0; q[1] = o1;
}

// ---------------------------------------------------------------------------
// Dual-job bf16 GEMM (BM=128): BK=64, 3-stage cp.async, ldmatrix (launch A).
// ---------------------------------------------------------------------------
#define GBK 64
#define GROW32 36
#define GTILE_U32 (128 * GROW32)
#define GEMM_SMEM (6 * GTILE_U32 * 4)

__global__ __launch_bounds__(256, 2)
void gemm_dual(const bf16* __restrict__ A0, const bf16* __restrict__ B0,
               const float* __restrict__ bias0, float* __restrict__ Cf0,
               bf16* __restrict__ Cb0, float scale0, int K0,
               const bf16* __restrict__ A1, const bf16* __restrict__ B1,
               const float* __restrict__ bias1, float* __restrict__ Cf1,
               bf16* __restrict__ Cb1, float scale1, int K1,
               int ycut)
{
    extern __shared__ uint32_t smem_g[];
    uint32_t* As[3] = { smem_g, smem_g + GTILE_U32, smem_g + 2 * GTILE_U32 };
    uint32_t* Bs[3] = { smem_g + 3 * GTILE_U32, smem_g + 4 * GTILE_U32,
                        smem_g + 5 * GTILE_U32 };

    const int tid    = threadIdx.x;
    const int lane   = tid & 31;
    const int warp   = tid >> 5;
    const int g      = lane >> 2;
    const int t      = lane & 3;
    const int warp_m = (warp & 3) * 32;
    const int warp_n = (warp >> 2) * 64;
    const int bm0    = blockIdx.x * 128;

    const bool j1 = ((int)blockIdx.y >= ycut);
    const bf16*  A     = j1 ? A1     : A0;
    const bf16*  Bw    = j1 ? B1     : B0;
    const float* bias  = j1 ? bias1  : bias0;
    float*       Cf    = j1 ? Cf1    : Cf0;
    bf16*        Cb    = j1 ? Cb1    : Cb0;
    const float  scale = j1 ? scale1 : scale0;
    const int    K     = j1 ? K1     : K0;
    const int    bn0   = (j1 ? (blockIdx.y - ycut) : blockIdx.y) * 128;

    float acc[2][8][4];
#pragma unroll
    for (int i = 0; i < 2; i++)
#pragma unroll
        for (int j = 0; j < 8; j++)
#pragma unroll
            for (int c = 0; c < 4; c++) acc[i][j][c] = 0.0f;

    const int kt_total = K / GBK;

    auto load_stage = [&](int kt, int buf) {
        int k0 = kt * GBK;
#pragma unroll
        for (int r = 0; r < 4; r++) {
            int c   = tid + r * 256;
            int row = c >> 3;
            int q16 = c & 7;
            uint32_t da = (uint32_t)__cvta_generic_to_shared(
                &As[buf][row * GROW32 + q16 * 4]);
            cp_async16(da, A + (size_t)(bm0 + row) * K + k0 + q16 * 8);
            uint32_t db = (uint32_t)__cvta_generic_to_shared(
                &Bs[buf][row * GROW32 + q16 * 4]);
            cp_async16(db, Bw + (size_t)(bn0 + row) * K + k0 + q16 * 8);
        }
    };

    load_stage(0, 0);
    asm volatile("cp.async.commit_group;\n");
    load_stage(1, 1);
    asm volatile("cp.async.commit_group;\n");

    const int arow_l = (lane & 7) + ((lane & 8) ? 8 : 0);
    const int adim_l = (lane & 16) ? 8 : 0;
    const int brow_l = (lane & 7) + ((lane & 16) ? 8 : 0);
    const int bdim_l = (lane & 8) ? 8 : 0;

    int buf = 0;
    for (int kt = 0; kt < kt_total; kt++) {
        asm volatile("cp.async.wait_group 1;\n");
        __syncthreads();
        if (kt + 2 < kt_total) {
            int nb = buf + 2; if (nb >= 3) nb -= 3;
            load_stage(kt + 2, nb);
            asm volatile("cp.async.commit_group;\n");
        } else {
            asm volatile("cp.async.commit_group;\n");
        }
        const bf16* abuf = (const bf16*)As[buf];
        const bf16* bbuf = (const bf16*)Bs[buf];
#pragma unroll
        for (int kg = 0; kg < 4; kg++) {
            uint32_t af[2][4];
#pragma unroll
            for (int mt = 0; mt < 2; mt++) {
                int arow = warp_m + mt * 16 + arow_l;
                uint32_t addr = (uint32_t)__cvta_generic_to_shared(
                    abuf + arow * 72 + kg * 16 + adim_l);
                ldsm_x4(af[mt][0], af[mt][1], af[mt][2], af[mt][3], addr);
            }
            uint32_t bfr[4][4];
#pragma unroll
            for (int nt2 = 0; nt2 < 4; nt2++) {
                int brow = warp_n + nt2 * 16 + brow_l;
                uint32_t addr = (uint32_t)__cvta_generic_to_shared(
                    bbuf + brow * 72 + kg * 16 + bdim_l);
                ldsm_x4(bfr[nt2][0], bfr[nt2][1], bfr[nt2][2], bfr[nt2][3], addr);
            }
#pragma unroll
            for (int mt = 0; mt < 2; mt++)
#pragma unroll
                for (int nt2 = 0; nt2 < 4; nt2++) {
                    mma_bf16(acc[mt][2*nt2][0], acc[mt][2*nt2][1],
                             acc[mt][2*nt2][2], acc[mt][2*nt2][3],
                             af[mt][0], af[mt][1], af[mt][2], af[mt][3],
                             bfr[nt2][0], bfr[nt2][1]);
                    mma_bf16(acc[mt][2*nt2+1][0], acc[mt][2*nt2+1][1],
                             acc[mt][2*nt2+1][2], acc[mt][2*nt2+1][3],
                             af[mt][0], af[mt][1], af[mt][2], af[mt][3],
                             bfr[nt2][2], bfr[nt2][3]);
                }
        }
        buf++; if (buf >= 3) buf -= 3;
    }

#pragma unroll
    for (int mt = 0; mt < 2; mt++) {
        int row0 = bm0 + warp_m + mt * 16 + g;
#pragma unroll
        for (int nt = 0; nt < 8; nt++) {
            int col = bn0 + warp_n + nt * 8 + t * 2;
            float2 bb = *(const float2*)(bias + col);
            float o00 = (acc[mt][nt][0] + bb.x) * scale;
            float o01 = (acc[mt][nt][1] + bb.y) * scale;
            float o10 = (acc[mt][nt][2] + bb.x) * scale;
            float o11 = (acc[mt][nt][3] + bb.y) * scale;
            if (Cf) {
                *(float2*)(Cf + (size_t)row0 * EMB + col)       = make_float2(o00, o01);
                *(float2*)(Cf + (size_t)(row0 + 8) * EMB + col) = make_float2(o10, o11);
            }
            if (Cb) {
                *(uint32_t*)((uint16_t*)Cb + (size_t)row0 * EMB + col)       = packbf(o01, o00);
                *(uint32_t*)((uint16_t*)Cb + (size_t)(row0 + 8) * EMB + col) = packbf(o11, o10);
            }
        }
    }
}

// ---------------------------------------------------------------------------
// gemm64: dual-job bf16 GEMM, BM=64, BN=128, BK=64, 2-stage, 3 CTAs/SM.
// Warp tile 16x64. bf16 output only. For K=512 launches (B and C).
// ---------------------------------------------------------------------------
#define G64_A_U32 (64 * GROW32)    // 2304
#define G64_B_U32 (128 * GROW32)   // 4608
#define G64_SMEM ((2 * G64_A_U32 + 2 * G64_B_U32) * 4)   // 55296 B

__global__ __launch_bounds__(256, 3)
void gemm64(const bf16* __restrict__ A0, const bf16* __restrict__ B0,
            const float* __restrict__ bias0, bf16* __restrict__ Cb0, float scale0,
            const bf16* __restrict__ A1, const bf16* __restrict__ B1,
            const float* __restrict__ bias1, bf16* __restrict__ Cb1, float scale1,
            int ycut)
{
    extern __shared__ uint32_t smem_g[];
    uint32_t* As[2] = { smem_g, smem_g + G64_A_U32 };
    uint32_t* Bs[2] = { smem_g + 2 * G64_A_U32,
                        smem_g + 2 * G64_A_U32 + G64_B_U32 };

    const int tid    = threadIdx.x;
    const int lane   = tid & 31;
    const int warp   = tid >> 5;
    const int g      = lane >> 2;
    const int t      = lane & 3;
    const int warp_m = (warp & 3) * 16;
    const int warp_n = (warp >> 2) * 64;
    const int bm0    = blockIdx.x * 64;
    const int K      = EMB;

    const bool j1 = ((int)blockIdx.y >= ycut);
    const bf16*  A     = j1 ? A1     : A0;
    const bf16*  Bw    = j1 ? B1     : B0;
    const float* bias  = j1 ? bias1  : bias0;
    bf16*        Cb    = j1 ? Cb1    : Cb0;
    const float  scale = j1 ? scale1 : scale0;
    const int    bn0   = (j1 ? (blockIdx.y - ycut) : blockIdx.y) * 128;

    float acc[8][4];
#pragma unroll
    for (int j = 0; j < 8; j++)
#pragma unroll
        for (int c = 0; c < 4; c++) acc[j][c] = 0.0f;

    const int kt_total = K / GBK;

    auto load_stage = [&](int kt, int buf) {
        int k0 = kt * GBK;
#pragma unroll
        for (int r = 0; r < 2; r++) {
            int c   = tid + r * 256;
            int row = c >> 3;
            int q16 = c & 7;
            uint32_t da = (uint32_t)__cvta_generic_to_shared(
                &As[buf][row * GROW32 + q16 * 4]);
            cp_async16(da, A + (size_t)(bm0 + row) * K + k0 + q16 * 8);
        }
#pragma unroll
        for (int r = 0; r < 4; r++) {
            int c   = tid + r * 256;
            int row = c >> 3;
            int q16 = c & 7;
            uint32_t db = (uint32_t)__cvta_generic_to_shared(
                &Bs[buf][row * GROW32 + q16 * 4]);
            cp_async16(db, Bw + (size_t)(bn0 + row) * K + k0 + q16 * 8);
        }
    };

    load_stage(0, 0);
    asm volatile("cp.async.commit_group;\n");

    const int arow_l = (lane & 7) + ((lane & 8) ? 8 : 0);
    const int adim_l = (lane & 16) ? 8 : 0;
    const int brow_l = (lane & 7) + ((lane & 16) ? 8 : 0);
    const int bdim_l = (lane & 8) ? 8 : 0;

    int buf = 0;
    for (int kt = 0; kt < kt_total; kt++) {
        asm volatile("cp.async.wait_group 0;\n");
        __syncthreads();
        if (kt + 1 < kt_total) {
            load_stage(kt + 1, buf ^ 1);
            asm volatile("cp.async.commit_group;\n");
        }
        const bf16* abuf = (const bf16*)As[buf];
        const bf16* bbuf = (const bf16*)Bs[buf];
#pragma unroll
        for (int kg = 0; kg < 4; kg++) {
            uint32_t af[4];
            {
                int arow = warp_m + arow_l;
                uint32_t addr = (uint32_t)__cvta_generic_to_shared(
                    abuf + arow * 72 + kg * 16 + adim_l);
                ldsm_x4(af[0], af[1], af[2], af[3], addr);
            }
            uint32_t bfr[4][4];
#pragma unroll
            for (int nt2 = 0; nt2 < 4; nt2++) {
                int brow = warp_n + nt2 * 16 + brow_l;
                uint32_t addr = (uint32_t)__cvta_generic_to_shared(
                    bbuf + brow * 72 + kg * 16 + bdim_l);
                ldsm_x4(bfr[nt2][0], bfr[nt2][1], bfr[nt2][2], bfr[nt2][3], addr);
            }
#pragma unroll
            for (int nt2 = 0; nt2 < 4; nt2++) {
                mma_bf16(acc[2*nt2][0], acc[2*nt2][1], acc[2*nt2][2], acc[2*nt2][3],
                         af[0], af[1], af[2], af[3], bfr[nt2][0], bfr[nt2][1]);
                mma_bf16(acc[2*nt2+1][0], acc[2*nt2+1][1], acc[2*nt2+1][2], acc[2*nt2+1][3],
                         af[0], af[1], af[2], af[3], bfr[nt2][2], bfr[nt2][3]);
            }
        }
        buf ^= 1;
    }

    const int row0 = bm0 + warp_m + g;
#pragma unroll
    for (int nt = 0; nt < 8; nt++) {
        int col = bn0 + warp_n + nt * 8 + t * 2;
        float2 bb = *(const float2*)(bias + col);
        float o00 = (acc[nt][0] + bb.x) * scale;
        float o01 = (acc[nt][1] + bb.y) * scale;
        float o10 = (acc[nt][2] + bb.x) * scale;
        float o11 = (acc[nt][3] + bb.y) * scale;
        *(uint32_t*)((uint16_t*)Cb + (size_t)row0 * EMB + col)       = packbf(o01, o00);
        *(uint32_t*)((uint16_t*)Cb + (size_t)(row0 + 8) * EMB + col) = packbf(o11, o10);
    }
}

// ---------------------------------------------------------------------------
// bf16 flash attention (R13): no-max exp2 softmax, split-half S/PV, 3 CTAs/SM.
// ---------------------------------------------------------------------------
#define FSTR32 36
#define ROWB   144

__global__ __launch_bounds__(256, 3)
void flash_bf16(const bf16* __restrict__ q, const bf16* __restrict__ k,
                const bf16* __restrict__ v, bf16* __restrict__ outp)
{
    const int b    = NGRAPH - 1 - blockIdx.x;
    const int h    = blockIdx.y;
    const int tile = blockIdx.z;
    const int len  = 256 + 8 * b;
    if (tile * 128 >= len) return;
    const int off  = 256 * b + 4 * b * (b - 1);

    const int tid  = threadIdx.x;
    const int lane = tid & 31;
    const int warp = tid >> 5;
    const int g    = lane >> 2;
    const int t    = lane & 3;

    __shared__ uint32_t Qs[128 * FSTR32];
    __shared__ uint32_t Ks[2][64 * FSTR32];
    __shared__ uint32_t Vs[2][64 * FSTR32];

    const uint32_t qbase  = (uint32_t)__cvta_generic_to_shared(Qs);
    const uint32_t kbase0 = (uint32_t)__cvta_generic_to_shared(Ks[0]);
    const uint32_t kbase1 = (uint32_t)__cvta_generic_to_shared(Ks[1]);
    const uint32_t vbase0 = (uint32_t)__cvta_generic_to_shared(Vs[0]);
    const uint32_t vbase1 = (uint32_t)__cvta_generic_to_shared(Vs[1]);

#pragma unroll
    for (int r = 0; r < 4; r++) {
        int c   = tid + r * 256;
        int row = c >> 3;
        int q16 = c & 7;
        int grow = off + min(tile * 128 + row, len - 1);
        cp_async16(qbase + row * ROWB + q16 * 16,
                   q + (size_t)grow * EMB + h * HD + q16 * 8);
    }
    asm volatile("cp.async.commit_group;\n");

    const int ntiles = (len + 63) >> 6;

    auto load_kv = [&](int jt, uint32_t kb, uint32_t vb) {
        int j0 = jt * 64;
        int cnt = min(64, len - j0);
#pragma unroll
        for (int r = 0; r < 2; r++) {
            int c   = tid + r * 256;
            int row = c >> 3;
            int q16 = c & 7;
            int grow = off + j0 + min(row, cnt - 1);
            cp_async16(kb + row * ROWB + q16 * 16,
                       k + (size_t)grow * EMB + h * HD + q16 * 8);
            cp_async16(vb + row * ROWB + q16 * 16,
                       v + (size_t)grow * EMB + h * HD + q16 * 8);
        }
    };

    load_kv(0, kbase0, vbase0);
    asm volatile("cp.async.commit_group;\n");

    asm volatile("cp.async.wait_group 1;\n");
    __syncthreads();

    uint32_t qf[4][4];
    {
        int arow = warp * 16 + (lane & 7) + ((lane & 8) ? 8 : 0);
        uint32_t a0 = qbase + arow * ROWB + ((lane & 16) ? 16 : 0);
#pragma unroll
        for (int kg = 0; kg < 4; kg++)
            ldsm_x4(qf[kg][0], qf[kg][1], qf[kg][2], qf[kg][3], a0 + kg * 32);
    }

    float oacc[8][4];
#pragma unroll
    for (int nt = 0; nt < 8; nt++)
#pragma unroll
        for (int c = 0; c < 4; c++) oacc[nt][c] = 0.0f;
    float l0 = 0.0f, l1 = 0.0f;

    const uint32_t koff = ((lane & 7) + ((lane & 16) ? 8 : 0)) * ROWB + ((lane & 8) ? 16 : 0);
    const uint32_t voff = ((lane & 7) + ((lane & 8) ? 8 : 0)) * ROWB + ((lane & 16) ? 16 : 0);

    for (int jt = 0; jt < ntiles; jt++) {
        const int cnt = min(64, len - jt * 64);
        const uint32_t kb = (jt & 1) ? kbase1 : kbase0;
        const uint32_t vb = (jt & 1) ? vbase1 : vbase0;

        asm volatile("cp.async.wait_group 0;\n");
        __syncthreads();
        if (jt + 1 < ntiles) {
            load_kv(jt + 1, (jt & 1) ? kbase0 : kbase1, (jt & 1) ? vbase0 : vbase1);
            asm volatile("cp.async.commit_group;\n");
        }

        const uint32_t kl = kb + koff;
        const uint32_t vl = vb + voff;

#pragma unroll
        for (int half = 0; half < 2; half++) {
            if (half * 32 >= cnt) break;
            const uint32_t klh = kl + half * (32 * ROWB);
            const uint32_t vlh = vl + half * (32 * ROWB);

            float cf[4][4];
#pragma unroll
            for (int nt = 0; nt < 4; nt++)
                cf[nt][0] = cf[nt][1] = cf[nt][2] = cf[nt][3] = 0.0f;

#pragma unroll
            for (int nt2 = 0; nt2 < 2; nt2++) {
                if (half * 32 + nt2 * 16 >= cnt) break;
#pragma unroll
                for (int kg = 0; kg < 4; kg++) {
                    uint32_t b00, b01, b10, b11;
                    ldsm_x4(b00, b01, b10, b11, klh + nt2 * (16 * ROWB) + kg * 32);
                    mma_bf16(cf[2*nt2][0], cf[2*nt2][1], cf[2*nt2][2], cf[2*nt2][3],
                             qf[kg][0], qf[kg][1], qf[kg][2], qf[kg][3], b00, b01);
                    mma_bf16(cf[2*nt2+1][0], cf[2*nt2+1][1], cf[2*nt2+1][2], cf[2*nt2+1][3],
                             qf[kg][0], qf[kg][1], qf[kg][2], qf[kg][3], b10, b11);
                }
            }
#pragma unroll
            for (int nt = 0; nt < 4; nt++)
                if (half * 32 + nt * 8 >= cnt)
                    cf[nt][0] = cf[nt][1] = cf[nt][2] = cf[nt][3] = -1e30f;

#pragma unroll
            for (int nt = 0; nt < 4; nt++) {
                cf[nt][0] = exp2f(cf[nt][0]);
                cf[nt][1] = exp2f(cf[nt][1]);
                cf[nt][2] = exp2f(cf[nt][2]);
                cf[nt][3] = exp2f(cf[nt][3]);
                l0 += cf[nt][0] + cf[nt][1];
                l1 += cf[nt][2] + cf[nt][3];
            }

#pragma unroll
            for (int kc = 0; kc < 2; kc++) {
                if (half * 32 + kc * 16 >= cnt) break;
                uint32_t a0 = packbf(cf[2*kc][1],   cf[2*kc][0]);
                uint32_t a1 = packbf(cf[2*kc][3],   cf[2*kc][2]);
                uint32_t a2 = packbf(cf[2*kc+1][1], cf[2*kc+1][0]);
                uint32_t a3 = packbf(cf[2*kc+1][3], cf[2*kc+1][2]);
#pragma unroll
                for (int nt2 = 0; nt2 < 4; nt2++) {
                    uint32_t b00, b01, b10, b11;
                    ldsm_x4_t(b00, b01, b10, b11, vlh + kc * (16 * ROWB) + nt2 * 32);
                    mma_bf16(oacc[2*nt2][0], oacc[2*nt2][1], oacc[2*nt2][2], oacc[2*nt2][3],
                             a0, a1, a2, a3, b00, b01);
                    mma_bf16(oacc[2*nt2+1][0], oacc[2*nt2+1][1], oacc[2*nt2+1][2], oacc[2*nt2+1][3],
                             a0, a1, a2, a3, b10, b11);
                }
            }
        }
    }

    l0 += __shfl_xor_sync(0xffffffffu, l0, 1);
    l0 += __shfl_xor_sync(0xffffffffu, l0, 2);
    l1 += __shfl_xor_sync(0xffffffffu, l1, 1);
    l1 += __shfl_xor_sync(0xffffffffu, l1, 2);

    const float li0 = 1.0f / l0;
    const float li1 = 1.0f / l1;
    const int qrow0 = tile * 128 + warp * 16 + g;
    uint16_t* ob = (uint16_t*)outp;
#pragma unroll
    for (int nt = 0; nt < 8; nt++) {
        int col = h * HD + nt * 8 + t * 2;
        if (qrow0 < len)
            *(uint32_t*)(ob + (size_t)(off + qrow0) * EMB + col) =
                packbf(oacc[nt][1] * li0, oacc[nt][0] * li0);
        if (qrow0 + 8 < len)
            *(uint32_t*)(ob + (size_t)(off + qrow0 + 8) * EMB + col) =
                packbf(oacc[nt][3] * li1, oacc[nt][2] * li1);
    }
}

// ---------------------------------------------------------------------------
// Residual + LayerNorm: x in bf16, residual fp32, out fp32. 2 rows per block.
// ---------------------------------------------------------------------------
__global__ __launch_bounds__(256)
void ln_kernel(const bf16* __restrict__ x, const float* __restrict__ res,
               const float* __restrict__ gamma, const float* __restrict__ beta,
               float* __restrict__ outp)
{
    const int half = threadIdx.x >> 7;
    const int row  = blockIdx.x * 2 + half;
    const int tid  = threadIdx.x & 127;

    uint2 xb = *(const uint2*)((const uint16_t*)x + (size_t)row * EMB + tid * 4);
    float x0 = __uint_as_float(xb.x << 16);
    float x1 = __uint_as_float(xb.x & 0xffff0000u);
    float x2 = __uint_as_float(xb.y << 16);
    float x3 = __uint_as_float(xb.y & 0xffff0000u);
    float4 rv = *(const float4*)(res + (size_t)row * EMB + tid * 4);
    float v0 = x0 + rv.x, v1 = x1 + rv.y, v2 = x2 + rv.z, v3 = x3 + rv.w;

    float s  = v0 + v1 + v2 + v3;
    float sq = v0*v0 + v1*v1 + v2*v2 + v3*v3;
#pragma unroll
    for (int o2 = 16; o2 > 0; o2 >>= 1) {
        s  += __shfl_xor_sync(0xffffffffu, s,  o2);
        sq += __shfl_xor_sync(0xffffffffu, sq, o2);
    }
    __shared__ float ss[8], ssq[8];
    int w = threadIdx.x >> 5;
    if ((threadIdx.x & 31) == 0) { ss[w] = s; ssq[w] = sq; }
    __syncthreads();
    int wb = half * 4;
    s  = ss[wb]  + ss[wb+1]  + ss[wb+2]  + ss[wb+3];
    sq = ssq[wb] + ssq[wb+1] + ssq[wb+2] + ssq[wb+3];

    float mu   = s * (1.0f / 512.0f);
    float var  = sq * (1.0f / 512.0f) - mu * mu;
    float rstd = rsqrtf(var + 1e-5f);

    float4 gv = *(const float4*)(gamma + tid * 4);
    float4 bv = *(const float4*)(beta  + tid * 4);
    float4 o;
    o.x = (v0 - mu) * rstd * gv.x + bv.x;
    o.y = (v1 - mu) * rstd * gv.y + bv.y;
    o.z = (v2 - mu) * rstd * gv.z + bv.z;
    o.w = (v3 - mu) * rstd * gv.w + bv.w;
    *(float4*)(outp + (size_t)row * EMB + tid * 4) = o;
}

// ---------------------------------------------------------------------------
extern "C" void kernel_launch(void* const* d_in, const int* in_sizes, int n_in,
                              void* d_out, int out_size)
{
    const float* esm   = (const float*)d_in[0];
    const float* h     = (const float*)d_in[1];
    const float* W_esm = (const float*)d_in[2];
    const float* b_esm = (const float*)d_in[3];
    const float* Wq    = (const float*)d_in[4];
    const float* bq    = (const float*)d_in[5];
    const float* Wk    = (const float*)d_in[6];
    const float* bk    = (const float*)d_in[7];
    const float* Wv    = (const float*)d_in[8];
    const float* bv    = (const float*)d_in[9];
    const float* Wo    = (const float*)d_in[10];
    const float* bo    = (const float*)d_in[11];
    const float* gamma = (const float*)d_in[12];
    const float* beta  = (const float*)d_in[13];
    float* out = (float*)d_out;

    bf16 *esm_bf, *h_bf, *Wesm_bf, *Wq_bf, *Wkv_bf, *Wo_bf;
    bf16 *hesm_bf, *q_bf, *k_bf, *v_bf, *ab_bf, *ob_bf;
    cudaGetSymbolAddress((void**)&esm_bf,  g_esm_bf);
    cudaGetSymbolAddress((void**)&h_bf,    g_h_bf);
    cudaGetSymbolAddress((void**)&Wesm_bf, g_Wesm_bf);
    cudaGetSymbolAddress((void**)&Wq_bf,   g_Wq_bf);
    cudaGetSymbolAddress((void**)&Wkv_bf,  g_Wkv_bf);
    cudaGetSymbolAddress((void**)&Wo_bf,   g_Wo_bf);
    cudaGetSymbolAddress((void**)&hesm_bf, g_hesm_bf);
    cudaGetSymbolAddress((void**)&q_bf,    g_q_bf);
    cudaGetSymbolAddress((void**)&k_bf,    g_k_bf);
    cudaGetSymbolAddress((void**)&v_bf,    g_v_bf);
    cudaGetSymbolAddress((void**)&ab_bf,   g_ab_bf);
    cudaGetSymbolAddress((void**)&ob_bf,   g_ob_bf);

    cudaFuncSetAttribute(gemm_dual, cudaFuncAttributeMaxDynamicSharedMemorySize,
                         GEMM_SMEM);
    cudaFuncSetAttribute(gemm64, cudaFuncAttributeMaxDynamicSharedMemorySize,
                         G64_SMEM);

    convert_all<<<(E6 + 255) / 256, 256>>>(esm, h, W_esm, Wq, Wk, Wv, Wo,
                                           esm_bf, h_bf, Wesm_bf, Wq_bf, Wkv_bf, Wo_bf);

    const float QSCALE = 0.125f * 1.4426950408889634f;

    // Launch A: ESM projection (K=1280) + Q projection (K=512), BM=128
    gemm_dual<<<dim3(N_TOTAL / 128, 8), 256, GEMM_SMEM>>>(
        esm_bf, Wesm_bf, b_esm, nullptr, hesm_bf, 1.0f,   ESM,
        h_bf,   Wq_bf,   bq,    nullptr, q_bf,    QSCALE, EMB,
        4);

    // Launch B: K + V projections, BM=64 (3 CTAs/SM)
    gemm64<<<dim3(N_TOTAL / 64, 8), 256, G64_SMEM>>>(
        hesm_bf, Wkv_bf,           bk, k_bf, 1.0f,
        hesm_bf, Wkv_bf + EMB*EMB, bv, v_bf, 1.0f,
        4);

    flash_bf16<<<dim3(NGRAPH, HEADS, 4), 256>>>(q_bf, k_bf, v_bf, ab_bf);

    // Launch C: Wo projection, BM=64, bf16 out
    gemm64<<<dim3(N_TOTAL / 64, 4), 256, G64_SMEM>>>(
        ab_bf, Wo_bf, bo, ob_bf, 1.0f,
        ab_bf, Wo_bf, bo, ob_bf, 1.0f,
        4);

    ln_kernel<<<N_TOTAL / 2, 256>>>(ob_bf, h, gamma, beta, out);
}